// round 13
// baseline (speedup 1.0000x reference)
#include <cuda_runtime.h>
#include <cuda_fp16.h>
#include <cstdint>

// ---------------- problem dims ----------------
#define MDIM 16384   // B*S
#define NDIM 1024    // DM
#define KDIM 1024    // DM

// ---------------- GEMM tiling: CTA 128x128, 4 warps of 64x64 ----------------
#define BM 128
#define BN 128
#define BK 64
#define NT (KDIM / BK)              // 16 k-stages
#define A_STAGE 16384               // 128x64 fp16
#define B_STAGE 16384               // 128x64 fp16
#define STAGE_BYTES (A_STAGE + B_STAGE)   // 32KB
#define GEMM_SMEM (3 * STAGE_BYTES + 64)  // 98368; 2 CTAs/SM

// packed sizes (uint4 units). chunk = 128 rows x 64 cols fp16 = 16KB = 1024 uint4
#define CHUNK_U4   1024
#define ACT_CHUNKS ((MDIM / 128) * NT)
#define W_CHUNKS   ((NDIM / 128) * NT)
#define ACT_PACK_U4 ((size_t)ACT_CHUNKS * CHUNK_U4)
#define W_PACK_U4   ((size_t)W_CHUNKS * CHUNK_U4)

// ---------------- scratch (no allocs allowed) ----------------
__device__ __half g_q[(size_t)MDIM * NDIM];
__device__ __half g_k[(size_t)MDIM * NDIM];
__device__ __half g_v[(size_t)MDIM * NDIM];
__device__ uint4  g_wp[4ull * W_PACK_U4];              // packed fp16 weights
__device__ uint4  g_qp[ACT_PACK_U4];
__device__ uint4  g_kp[ACT_PACK_U4];
__device__ uint4  g_vp[ACT_PACK_U4];
__device__ uint4  g_ap[ACT_PACK_U4];                   // packed attn output

// ---------------- helpers ----------------
__device__ __forceinline__ uint32_t smem_u32(const void* p) {
    uint32_t a;
    asm("{ .reg .u64 t; cvta.to.shared.u64 t, %1; cvt.u32.u64 %0, t; }" : "=r"(a) : "l"(p));
    return a;
}

__device__ __forceinline__ void cp_async16(uint32_t saddr, const void* gaddr) {
    asm volatile("cp.async.cg.shared.global [%0], [%1], 16;\n" :: "r"(saddr), "l"(gaddr));
}

__device__ __forceinline__ void lds128(uint32_t& a, uint32_t& b, uint32_t& c, uint32_t& d,
                                       uint32_t addr) {
    asm volatile("ld.shared.v4.b32 {%0,%1,%2,%3}, [%4];"
                 : "=r"(a), "=r"(b), "=r"(c), "=r"(d) : "r"(addr));
}

__device__ __forceinline__ void mma_f16(float c[4], const uint32_t a[4],
                                        uint32_t b0, uint32_t b1) {
    asm volatile(
        "mma.sync.aligned.m16n8k16.row.col.f32.f16.f16.f32 "
        "{%0,%1,%2,%3}, {%4,%5,%6,%7}, {%8,%9}, {%0,%1,%2,%3};\n"
        : "+f"(c[0]), "+f"(c[1]), "+f"(c[2]), "+f"(c[3])
        : "r"(a[0]), "r"(a[1]), "r"(a[2]), "r"(a[3]), "r"(b0), "r"(b1));
}

__device__ __forceinline__ void ldsm4(uint32_t r[4], uint32_t addr) {
    asm volatile("ldmatrix.sync.aligned.m8n8.x4.shared.b16 {%0,%1,%2,%3}, [%4];"
                 : "=r"(r[0]), "=r"(r[1]), "=r"(r[2]), "=r"(r[3]) : "r"(addr));
}

__device__ __forceinline__ void ldsm4t(uint32_t r[4], uint32_t addr) {
    asm volatile("ldmatrix.sync.aligned.m8n8.x4.trans.shared.b16 {%0,%1,%2,%3}, [%4];"
                 : "=r"(r[0]), "=r"(r[1]), "=r"(r[2]), "=r"(r[3]) : "r"(addr));
}

__device__ __forceinline__ uint32_t ph2(float lo, float hi) {
    __half2 h = __floats2half2_rn(lo, hi);
    return *reinterpret_cast<uint32_t*>(&h);
}

__device__ __forceinline__ void store2(float* p, float a, float b) {
    *(float2*)p = make_float2(a, b);
}
__device__ __forceinline__ void store2(__half* p, float a, float b) {
    *(uint32_t*)p = ph2(a, b);
}

#define MBAR_INIT(a, n) asm volatile("mbarrier.init.shared.b64 [%0], %1;" :: "r"(a), "r"(n) : "memory")
#define MBAR_ARRIVE(a)  asm volatile("mbarrier.arrive.shared.b64 _, [%0];" :: "r"(a) : "memory")
#define CP_MBAR_ARRIVE(a) asm volatile("cp.async.mbarrier.arrive.noinc.shared.b64 [%0];" :: "r"(a) : "memory")

__device__ __forceinline__ void mbar_wait(uint32_t addr, uint32_t parity) {
    uint32_t done;
    asm volatile("{ .reg .pred p; mbarrier.try_wait.parity.acquire.cta.shared::cta.b64 p, [%1], %2; selp.b32 %0,1,0,p; }"
                 : "=r"(done) : "r"(addr), "r"(parity) : "memory");
    if (!done) {
        asm volatile(
            "{ .reg .pred P1;\n"
            "W_%=: mbarrier.try_wait.parity.acquire.cta.shared::cta.b64 P1, [%0], %1, 0x989680;\n"
            "@P1 bra.uni D_%=;\n"
            "bra.uni W_%=;\n"
            "D_%=: }" :: "r"(addr), "r"(parity) : "memory");
    }
}

// ---------------- weight pack: W[k][n] f32 -> fragment-packed fp16 ----------
__global__ void wpack(const float* __restrict__ W0, const float* __restrict__ W1,
                      const float* __restrict__ W2, const float* __restrict__ W3,
                      uint4* __restrict__ out)
{
    __shared__ float s[128 * 66];
    const int z = blockIdx.z;
    const float* W = (z == 0) ? W0 : (z == 1) ? W1 : (z == 2) ? W2 : W3;
    uint4* dst = out + (size_t)z * W_PACK_U4
               + ((size_t)(blockIdx.y * NT + blockIdx.x)) * CHUNK_U4;
    const int t = threadIdx.x;
    const int kt = blockIdx.x, nblk = blockIdx.y;
#pragma unroll
    for (int i = 0; i < 32; i++) {
        int idx = t + i * 256;
        int k = idx >> 7, n = idx & 127;
        s[n * 66 + k] = W[(size_t)(kt * 64 + k) * NDIM + nblk * 128 + n];
    }
    __syncthreads();
    const int b = t >> 5, l = t & 31, grp = l >> 2, tig = l & 3;
    const int r0 = (b * 16 + grp) * 66, r1 = r0 + 8 * 66;
    uint4* base = dst + b * 32 + l;
#pragma unroll
    for (int ks = 0; ks < 4; ks++) {
        const int c = ks * 16 + 2 * tig;
        float2 x0 = *(const float2*)&s[r0 + c];
        float2 x1 = *(const float2*)&s[r1 + c];
        float2 x2 = *(const float2*)&s[r0 + c + 8];
        float2 x3 = *(const float2*)&s[r1 + c + 8];
        uint4 o;
        o.x = ph2(x0.x, x0.y);
        o.y = ph2(x1.x, x1.y);
        o.z = ph2(x2.x, x2.y);
        o.w = ph2(x3.x, x3.y);
        base[ks * 256] = o;
    }
}

// ---------------- activation pack: f32 row-major -> fp16 frags ----------------
__device__ __forceinline__ void apack_body(const float* __restrict__ src,
                                           uint4* __restrict__ dst)
{
    __shared__ float s[128 * 68];
    const int t = threadIdx.x;
    const int mblk = blockIdx.y, kt = blockIdx.x;
#pragma unroll
    for (int i = 0; i < 8; i++) {
        int idx = t + i * 256;
        int row = idx >> 4, c4 = (idx & 15) * 4;
        *(float4*)&s[row * 68 + c4] =
            *(const float4*)&src[(size_t)(mblk * 128 + row) * KDIM + kt * 64 + c4];
    }
    __syncthreads();
    const int b = t >> 5, l = t & 31, grp = l >> 2, tig = l & 3;
    const int r0 = (b * 16 + grp) * 68, r1 = r0 + 8 * 68;
    uint4* base = dst + ((size_t)(mblk * NT + kt)) * CHUNK_U4 + b * 32 + l;
#pragma unroll
    for (int ks = 0; ks < 4; ks++) {
        const int c = ks * 16 + 2 * tig;
        float2 x0 = *(const float2*)&s[r0 + c];
        float2 x1 = *(const float2*)&s[r1 + c];
        float2 x2 = *(const float2*)&s[r0 + c + 8];
        float2 x3 = *(const float2*)&s[r1 + c + 8];
        uint4 o;
        o.x = ph2(x0.x, x0.y);
        o.y = ph2(x1.x, x1.y);
        o.z = ph2(x2.x, x2.y);
        o.w = ph2(x3.x, x3.y);
        base[ks * 256] = o;
    }
}

__global__ void apack_qkv(const float* __restrict__ Q, const float* __restrict__ K,
                          const float* __restrict__ V)
{
    const int z = blockIdx.z;
    apack_body(z == 0 ? Q : z == 1 ? K : V,
               z == 0 ? g_qp : z == 1 ? g_kp : g_vp);
}

// ---------------- fp16 tensor-core GEMM: 64x64 warp tiles, mbarrier ring --------
// CTA 128x128, 4 warps (2x2). Per ks: 8 lds128 -> 32 HMMA (4 B/HMMA smem ratio).
template <typename OutT>
__device__ __forceinline__ void gemm_body(const uint4* __restrict__ Ap,
                                          const uint4* __restrict__ Bp,
                                          const float* __restrict__ bias,
                                          OutT* __restrict__ C, OutT* __restrict__ C2,
                                          uint32_t sb)
{
    const int tid = threadIdx.x;               // 128 threads
    const int wid = tid >> 5, lane = tid & 31;
    const int grp = lane >> 2, tig = lane & 3;
    const int wm = wid >> 1, wn = wid & 1;     // 2x2 warps, 64x64 each
    const int mblk = blockIdx.y, bx = blockIdx.x;

    const uint32_t mb = sb + 3 * STAGE_BYTES;
    if (tid == 0) {
#pragma unroll
        for (int s = 0; s < 3; s++) {
            MBAR_INIT(mb + s * 8, 128);        // full: 128 cp-completion arrivals
            MBAR_INIT(mb + 24 + s * 8, 128);   // empty: 128 consumer arrivals
        }
    }
    __syncthreads();

    float acc[4][8][4];
#pragma unroll
    for (int mi = 0; mi < 4; mi++)
#pragma unroll
        for (int ni = 0; ni < 8; ni++)
#pragma unroll
            for (int r = 0; r < 4; r++) acc[mi][ni][r] = 0.f;

    const uint4* Abase = Ap + (size_t)mblk * NT * CHUNK_U4 + tid * 8;
    const uint4* Bbase = Bp + (size_t)bx * NT * CHUNK_U4 + tid * 8;

    auto produce = [&](int pk) {
        const int s2 = pk % 3;
        if (pk >= 3) mbar_wait(mb + 24 + s2 * 8, ((pk / 3) - 1) & 1);
        const uint32_t da = sb + s2 * STAGE_BYTES + tid * 128;
        const uint4* sa = Abase + (size_t)pk * CHUNK_U4;
#pragma unroll
        for (int i = 0; i < 8; i++) cp_async16(da + i * 16, sa + i);
        const uint32_t db = sb + s2 * STAGE_BYTES + A_STAGE + tid * 128;
        const uint4* sbp = Bbase + (size_t)pk * CHUNK_U4;
#pragma unroll
        for (int i = 0; i < 8; i++) cp_async16(db + i * 16, sbp + i);
        CP_MBAR_ARRIVE(mb + s2 * 8);
    };

    produce(0);
    produce(1);

    const uint32_t aOff = wm * 2048 + lane * 16;            // b-blocks 4wm..4wm+3
    const uint32_t bOff = A_STAGE + wn * 2048 + lane * 16;  // b-blocks 4wn..4wn+3

    int fph = 0;
    for (int kt = 0; kt < NT; kt++) {
        const int s = kt % 3;
        mbar_wait(mb + s * 8, fph);
        if (kt + 2 < NT) produce(kt + 2);

        const uint32_t aBase = sb + s * STAGE_BYTES + aOff;
        const uint32_t bBase = sb + s * STAGE_BYTES + bOff;
#pragma unroll
        for (int ks = 0; ks < 4; ks++) {
            uint32_t a4[4][4], b4[4][4];
#pragma unroll
            for (int mi = 0; mi < 4; mi++)
                lds128(a4[mi][0], a4[mi][1], a4[mi][2], a4[mi][3],
                       aBase + ks * 4096 + mi * 512);
#pragma unroll
            for (int nb = 0; nb < 4; nb++)
                lds128(b4[nb][0], b4[nb][1], b4[nb][2], b4[nb][3],
                       bBase + ks * 4096 + nb * 512);
#pragma unroll
            for (int mi = 0; mi < 4; mi++) {
#pragma unroll
                for (int nb = 0; nb < 4; nb++) {
                    mma_f16(acc[mi][nb * 2 + 0], a4[mi], b4[nb][0], b4[nb][2]);
                    mma_f16(acc[mi][nb * 2 + 1], a4[mi], b4[nb][1], b4[nb][3]);
                }
            }
        }
        MBAR_ARRIVE(mb + 24 + s * 8);
        if (s == 2) fph ^= 1;
    }

    // ---- epilogue: +bias, store (optionally duplicated) ----
    const int n0 = bx * BN + wn * 64;
    const int m0 = mblk * BM + wm * 64;
#pragma unroll
    for (int mi = 0; mi < 4; mi++) {
        const int r0 = m0 + mi * 16 + grp;
#pragma unroll
        for (int ni = 0; ni < 8; ni++) {
            const int col = n0 + (ni >> 1) * 16 + (ni & 1) * 8 + tig * 2;
            float2 bv = *(const float2*)&bias[col];
            store2(&C[(size_t)r0 * NDIM + col], acc[mi][ni][0] + bv.x, acc[mi][ni][1] + bv.y);
            store2(&C[(size_t)(r0 + 8) * NDIM + col], acc[mi][ni][2] + bv.x, acc[mi][ni][3] + bv.y);
            if (C2) {
                store2(&C2[(size_t)r0 * NDIM + col], acc[mi][ni][0] + bv.x, acc[mi][ni][1] + bv.y);
                store2(&C2[(size_t)(r0 + 8) * NDIM + col], acc[mi][ni][2] + bv.x, acc[mi][ni][3] + bv.y);
            }
        }
    }
}

__global__ void __launch_bounds__(128, 2) gemm_qkv(
    const float* __restrict__ bq, const float* __restrict__ bk, const float* __restrict__ bv,
    __half* __restrict__ Cq, __half* __restrict__ Ck, __half* __restrict__ Cv)
{
    extern __shared__ char smem[];
    const int z = blockIdx.z;
    gemm_body<__half>(z == 0 ? g_qp : z == 1 ? g_kp : g_vp,
                      g_wp + (size_t)z * W_PACK_U4,
                      z == 0 ? bq : z == 1 ? bk : bv,
                      z == 0 ? Cq : z == 1 ? Ck : Cv, (__half*)nullptr, smem_u32(smem));
}

__global__ void __launch_bounds__(128, 2) gemm_out(
    const float* __restrict__ bias, float* __restrict__ C, float* __restrict__ C2)
{
    extern __shared__ char smem[];
    gemm_body<float>(g_ap, g_wp + 3ull * W_PACK_U4, bias, C, C2, smem_u32(smem));
}

// ---------------- fused tensor-core attention + fragment pack ----------------
#define ATW 8
#define STG_H 3456
#define SOUT_TS 1096
#define SOUT_HS 68
#define ATTN_SMEM ((ATW * STG_H + 16 * SOUT_TS) * 2)

__global__ void __launch_bounds__(256) attn_pack(
    const __half* __restrict__ qg, const __half* __restrict__ kg,
    const __half* __restrict__ vg, const float* __restrict__ mg)
{
    extern __shared__ __half smh[];
    const int warp = threadIdx.x >> 5, lane = threadIdx.x & 31;
    const int grp = lane >> 2, tig = lane & 3;
    __half* sq = smh + warp * STG_H;
    __half* sk = sq + 16 * 72;
    __half* sv = sk + 16 * 72;
    __half* sout = smh + ATW * STG_H;
    const uint32_t sqa = smem_u32(sq), ska = smem_u32(sk), sva = smem_u32(sv);

    const int lrow = (lane & 7) + ((lane >> 3) & 1) * 8;
    const int lc8  = (lane >> 4) * 8;

#pragma unroll
    for (int pass = 0; pass < 2; pass++) {
        const int lt = warp + pass * 8;
        const int tok = blockIdx.x * 16 + lt;
        const size_t base = (size_t)tok * 1024;

#pragma unroll
        for (int i = 0; i < 4; i++) {
            int idx = lane + i * 32;
            int row = idx >> 3, cq = (idx & 7) * 8;
            *(uint4*)&sq[row * 72 + cq] = *(const uint4*)&qg[base + row * 64 + cq];
            *(uint4*)&sk[row * 72 + cq] = *(const uint4*)&kg[base + row * 64 + cq];
            *(uint4*)&sv[row * 72 + cq] = *(const uint4*)&vg[base + row * 64 + cq];
        }
        __syncwarp();

        float s0[4] = {0.f, 0.f, 0.f, 0.f}, s1[4] = {0.f, 0.f, 0.f, 0.f};
#pragma unroll
        for (int ks = 0; ks < 4; ks++) {
            uint32_t qa[4], kb[4];
            ldsm4(qa, sqa + (lrow * 72 + ks * 16 + lc8) * 2);
            ldsm4(kb, ska + (lrow * 72 + ks * 16 + lc8) * 2);
            mma_f16(s0, qa, kb[0], kb[2]);
            mma_f16(s1, qa, kb[1], kb[3]);
        }

        const float* mp = mg + (size_t)tok * 256;
        float2 m00 = *(const float2*)&mp[grp * 16 + 2 * tig];
        float2 m01 = *(const float2*)&mp[grp * 16 + 8 + 2 * tig];
        float2 m10 = *(const float2*)&mp[(grp + 8) * 16 + 2 * tig];
        float2 m11 = *(const float2*)&mp[(grp + 8) * 16 + 8 + 2 * tig];
        float a0 = fmaf(m00.x, -1e9f, s0[0] * 0.125f);
        float a1 = fmaf(m00.y, -1e9f, s0[1] * 0.125f);
        float a2 = fmaf(m10.x, -1e9f, s0[2] * 0.125f);
        float a3 = fmaf(m10.y, -1e9f, s0[3] * 0.125f);
        float a4 = fmaf(m01.x, -1e9f, s1[0] * 0.125f);
        float a5 = fmaf(m01.y, -1e9f, s1[1] * 0.125f);
        float a6 = fmaf(m11.x, -1e9f, s1[2] * 0.125f);
        float a7 = fmaf(m11.y, -1e9f, s1[3] * 0.125f);

        float mxA = fmaxf(fmaxf(a0, a1), fmaxf(a4, a5));
        float mxB = fmaxf(fmaxf(a2, a3), fmaxf(a6, a7));
        mxA = fmaxf(mxA, __shfl_xor_sync(0xffffffffu, mxA, 1));
        mxA = fmaxf(mxA, __shfl_xor_sync(0xffffffffu, mxA, 2));
        mxB = fmaxf(mxB, __shfl_xor_sync(0xffffffffu, mxB, 1));
        mxB = fmaxf(mxB, __shfl_xor_sync(0xffffffffu, mxB, 2));

        float e0 = __expf(a0 - mxA), e1 = __expf(a1 - mxA);
        float e4 = __expf(a4 - mxA), e5 = __expf(a5 - mxA);
        float e2 = __expf(a2 - mxB), e3 = __expf(a3 - mxB);
        float e6 = __expf(a6 - mxB), e7 = __expf(a7 - mxB);

        float sA = e0 + e1 + e4 + e5;
        float sB = e2 + e3 + e6 + e7;
        sA += __shfl_xor_sync(0xffffffffu, sA, 1);
        sA += __shfl_xor_sync(0xffffffffu, sA, 2);
        sB += __shfl_xor_sync(0xffffffffu, sB, 1);
        sB += __shfl_xor_sync(0xffffffffu, sB, 2);
        const float iA = 1.0f / sA, iB = 1.0f / sB;

        uint32_t pf[4];
        pf[0] = ph2(e0 * iA, e1 * iA);
        pf[1] = ph2(e2 * iB, e3 * iB);
        pf[2] = ph2(e4 * iA, e5 * iA);
        pf[3] = ph2(e6 * iB, e7 * iB);

        float oc[8][4];
#pragma unroll
        for (int nt = 0; nt < 8; nt++)
#pragma unroll
            for (int r = 0; r < 4; r++) oc[nt][r] = 0.f;
#pragma unroll
        for (int cc = 0; cc < 4; cc++) {
            uint32_t vb[4];
            ldsm4t(vb, sva + (lrow * 72 + cc * 16 + lc8) * 2);
            mma_f16(oc[cc * 2 + 0], pf, vb[0], vb[1]);
            mma_f16(oc[cc * 2 + 1], pf, vb[2], vb[3]);
        }

        __half* so = sout + lt * SOUT_TS;
#pragma unroll
        for (int nt = 0; nt < 8; nt++) {
            *(uint32_t*)&so[grp * SOUT_HS + nt * 8 + 2 * tig]       = ph2(oc[nt][0], oc[nt][1]);
            *(uint32_t*)&so[(grp + 8) * SOUT_HS + nt * 8 + 2 * tig] = ph2(oc[nt][2], oc[nt][3]);
        }
        __syncwarp();
    }
    __syncthreads();

    const int mblk = blockIdx.x >> 3, b = blockIdx.x & 7;
#pragma unroll
    for (int i = 0; i < 8; i++) {
        const int g = warp * 8 + i;
        const int kt = g >> 2, ks = g & 3;
        const __half* s0p = sout + grp * SOUT_TS + kt * SOUT_HS + ks * 16 + 2 * tig;
        const __half* s1p = s0p + 8 * SOUT_TS;
        uint4 o;
        o.x = *(const uint32_t*)s0p;
        o.y = *(const uint32_t*)s1p;
        o.z = *(const uint32_t*)(s0p + 8);
        o.w = *(const uint32_t*)(s1p + 8);
        g_ap[((size_t)(mblk * NT + kt)) * CHUNK_U4 + ks * 256 + b * 32 + lane] = o;
    }
}

// ---------------- launch ----------------
extern "C" void kernel_launch(void* const* d_in, const int* in_sizes, int n_in,
                              void* d_out, int out_size)
{
    const float* Q  = (const float*)d_in[0];
    const float* K  = (const float*)d_in[1];
    const float* V  = (const float*)d_in[2];
    const float* Msk= (const float*)d_in[3];
    const float* Wq = (const float*)d_in[4];
    const float* bq = (const float*)d_in[5];
    const float* Wk = (const float*)d_in[6];
    const float* bk = (const float*)d_in[7];
    const float* Wv = (const float*)d_in[8];
    const float* bv = (const float*)d_in[9];
    const float* Wo = (const float*)d_in[10];
    const float* bo = (const float*)d_in[11];
    float* out = (float*)d_out;

    __half *gq, *gk, *gv;
    uint4* gwp;
    cudaGetSymbolAddress((void**)&gq, g_q);
    cudaGetSymbolAddress((void**)&gk, g_k);
    cudaGetSymbolAddress((void**)&gv, g_v);
    cudaGetSymbolAddress((void**)&gwp, g_wp);

    cudaFuncSetAttribute(gemm_qkv, cudaFuncAttributeMaxDynamicSharedMemorySize, GEMM_SMEM);
    cudaFuncSetAttribute(gemm_out, cudaFuncAttributeMaxDynamicSharedMemorySize, GEMM_SMEM);
    cudaFuncSetAttribute(attn_pack, cudaFuncAttributeMaxDynamicSharedMemorySize, ATTN_SMEM);

    // 1. pack weights + input activations
    wpack<<<dim3(NT, NDIM / 128, 4), 256>>>(Wq, Wk, Wv, Wo, gwp);
    apack_qkv<<<dim3(NT, MDIM / 128, 3), 256>>>(Q, K, V);

    // 2. QKV projections (fp16 out, 64x64 warp tiles)
    dim3 gg(NDIM / BN, MDIM / BM, 3);   // (8, 128, 3)
    gemm_qkv<<<gg, 128, GEMM_SMEM>>>(bq, bk, bv, gq, gk, gv);

    // 3. fused tensor-core attention + fragment pack (writes g_ap directly)
    attn_pack<<<MDIM / 16, 256, ATTN_SMEM>>>(gq, gk, gv, Msk);

    // 4. output projection
    float* out2 = ((long long)out_size >= 2LL * MDIM * NDIM) ? out + (size_t)MDIM * NDIM
                                                             : nullptr;
    dim3 go(NDIM / BN, MDIM / BM);      // (8, 128)
    gemm_out<<<go, 128, GEMM_SMEM>>>(bo, out, out2);
}

// round 14
// speedup vs baseline: 1.4280x; 1.4280x over previous
#include <cuda_runtime.h>
#include <cuda_fp16.h>
#include <cstdint>

// ---------------- problem dims ----------------
#define MDIM 16384   // B*S
#define NDIM 1024    // DM
#define KDIM 1024    // DM

// ---------------- GEMM tiling ----------------
#define BM 128
#define BN 64
#define BK 64
#define NT (KDIM / BK)              // 16 k-stages
#define A_STAGE 16384               // 128x64 fp16
#define B_STAGE 8192                // 64x64 fp16
#define STAGE_BYTES (A_STAGE + B_STAGE)   // 24KB
#define GEMM_SMEM (3 * STAGE_BYTES + 64)  // + mbarrier block

// packed sizes (uint4 units). chunk = 128 rows x 64 cols fp16 = 16KB = 1024 uint4
#define CHUNK_U4   1024
#define ACT_CHUNKS ((MDIM / 128) * NT)
#define W_CHUNKS   ((NDIM / 128) * NT)
#define ACT_PACK_U4 ((size_t)ACT_CHUNKS * CHUNK_U4)
#define W_PACK_U4   ((size_t)W_CHUNKS * CHUNK_U4)

// ---------------- scratch (no allocs allowed) ----------------
__device__ __half g_q[(size_t)MDIM * NDIM];
__device__ __half g_k[(size_t)MDIM * NDIM];
__device__ __half g_v[(size_t)MDIM * NDIM];
__device__ uint4  g_wp[4ull * W_PACK_U4];              // packed fp16 weights
__device__ uint4  g_qp[ACT_PACK_U4];
__device__ uint4  g_kp[ACT_PACK_U4];
__device__ uint4  g_vp[ACT_PACK_U4];
__device__ uint4  g_ap[ACT_PACK_U4];                   // packed attn output

// ---------------- helpers ----------------
__device__ __forceinline__ uint32_t smem_u32(const void* p) {
    uint32_t a;
    asm("{ .reg .u64 t; cvta.to.shared.u64 t, %1; cvt.u32.u64 %0, t; }" : "=r"(a) : "l"(p));
    return a;
}

__device__ __forceinline__ void cp_async16(uint32_t saddr, const void* gaddr) {
    asm volatile("cp.async.cg.shared.global [%0], [%1], 16;\n" :: "r"(saddr), "l"(gaddr));
}

__device__ __forceinline__ void lds128(uint32_t& a, uint32_t& b, uint32_t& c, uint32_t& d,
                                       uint32_t addr) {
    asm volatile("ld.shared.v4.b32 {%0,%1,%2,%3}, [%4];"
                 : "=r"(a), "=r"(b), "=r"(c), "=r"(d) : "r"(addr));
}

__device__ __forceinline__ void mma_f16(float c[4], const uint32_t a[4],
                                        uint32_t b0, uint32_t b1) {
    asm volatile(
        "mma.sync.aligned.m16n8k16.row.col.f32.f16.f16.f32 "
        "{%0,%1,%2,%3}, {%4,%5,%6,%7}, {%8,%9}, {%0,%1,%2,%3};\n"
        : "+f"(c[0]), "+f"(c[1]), "+f"(c[2]), "+f"(c[3])
        : "r"(a[0]), "r"(a[1]), "r"(a[2]), "r"(a[3]), "r"(b0), "r"(b1));
}

__device__ __forceinline__ void ldsm4(uint32_t r[4], uint32_t addr) {
    asm volatile("ldmatrix.sync.aligned.m8n8.x4.shared.b16 {%0,%1,%2,%3}, [%4];"
                 : "=r"(r[0]), "=r"(r[1]), "=r"(r[2]), "=r"(r[3]) : "r"(addr));
}

__device__ __forceinline__ void ldsm4t(uint32_t r[4], uint32_t addr) {
    asm volatile("ldmatrix.sync.aligned.m8n8.x4.trans.shared.b16 {%0,%1,%2,%3}, [%4];"
                 : "=r"(r[0]), "=r"(r[1]), "=r"(r[2]), "=r"(r[3]) : "r"(addr));
}

__device__ __forceinline__ uint32_t ph2(float lo, float hi) {
    __half2 h = __floats2half2_rn(lo, hi);
    return *reinterpret_cast<uint32_t*>(&h);
}

__device__ __forceinline__ void store2(float* p, float a, float b) {
    *(float2*)p = make_float2(a, b);
}
__device__ __forceinline__ void store2(__half* p, float a, float b) {
    *(uint32_t*)p = ph2(a, b);
}

#define MBAR_INIT(a, n) asm volatile("mbarrier.init.shared.b64 [%0], %1;" :: "r"(a), "r"(n) : "memory")
#define MBAR_ARRIVE(a)  asm volatile("mbarrier.arrive.shared.b64 _, [%0];" :: "r"(a) : "memory")
#define CP_MBAR_ARRIVE(a) asm volatile("cp.async.mbarrier.arrive.noinc.shared.b64 [%0];" :: "r"(a) : "memory")

__device__ __forceinline__ void mbar_wait(uint32_t addr, uint32_t parity) {
    uint32_t done;
    asm volatile("{ .reg .pred p; mbarrier.try_wait.parity.acquire.cta.shared::cta.b64 p, [%1], %2; selp.b32 %0,1,0,p; }"
                 : "=r"(done) : "r"(addr), "r"(parity) : "memory");
    if (!done) {
        asm volatile(
            "{ .reg .pred P1;\n"
            "W_%=: mbarrier.try_wait.parity.acquire.cta.shared::cta.b64 P1, [%0], %1, 0x989680;\n"
            "@P1 bra.uni D_%=;\n"
            "bra.uni W_%=;\n"
            "D_%=: }" :: "r"(addr), "r"(parity) : "memory");
    }
}

// ---------------- weight pack: W[k][n] f32 -> fragment-packed fp16 ----------
__global__ void wpack(const float* __restrict__ W0, const float* __restrict__ W1,
                      const float* __restrict__ W2, const float* __restrict__ W3,
                      uint4* __restrict__ out)
{
    __shared__ float s[128 * 66];
    const int z = blockIdx.z;
    const float* W = (z == 0) ? W0 : (z == 1) ? W1 : (z == 2) ? W2 : W3;
    uint4* dst = out + (size_t)z * W_PACK_U4
               + ((size_t)(blockIdx.y * NT + blockIdx.x)) * CHUNK_U4;
    const int t = threadIdx.x;
    const int kt = blockIdx.x, nblk = blockIdx.y;
#pragma unroll
    for (int i = 0; i < 32; i++) {
        int idx = t + i * 256;
        int k = idx >> 7, n = idx & 127;
        s[n * 66 + k] = W[(size_t)(kt * 64 + k) * NDIM + nblk * 128 + n];
    }
    __syncthreads();
    const int b = t >> 5, l = t & 31, grp = l >> 2, tig = l & 3;
    const int r0 = (b * 16 + grp) * 66, r1 = r0 + 8 * 66;
    uint4* base = dst + b * 32 + l;
#pragma unroll
    for (int ks = 0; ks < 4; ks++) {
        const int c = ks * 16 + 2 * tig;
        float2 x0 = *(const float2*)&s[r0 + c];
        float2 x1 = *(const float2*)&s[r1 + c];
        float2 x2 = *(const float2*)&s[r0 + c + 8];
        float2 x3 = *(const float2*)&s[r1 + c + 8];
        uint4 o;
        o.x = ph2(x0.x, x0.y);
        o.y = ph2(x1.x, x1.y);
        o.z = ph2(x2.x, x2.y);
        o.w = ph2(x3.x, x3.y);
        base[ks * 256] = o;
    }
}

// ---------------- activation pack: f32 row-major -> fp16 frags ----------------
__device__ __forceinline__ void apack_body(const float* __restrict__ src,
                                           uint4* __restrict__ dst)
{
    __shared__ float s[128 * 68];
    const int t = threadIdx.x;
    const int mblk = blockIdx.y, kt = blockIdx.x;
#pragma unroll
    for (int i = 0; i < 8; i++) {
        int idx = t + i * 256;
        int row = idx >> 4, c4 = (idx & 15) * 4;
        *(float4*)&s[row * 68 + c4] =
            *(const float4*)&src[(size_t)(mblk * 128 + row) * KDIM + kt * 64 + c4];
    }
    __syncthreads();
    const int b = t >> 5, l = t & 31, grp = l >> 2, tig = l & 3;
    const int r0 = (b * 16 + grp) * 68, r1 = r0 + 8 * 68;
    uint4* base = dst + ((size_t)(mblk * NT + kt)) * CHUNK_U4 + b * 32 + l;
#pragma unroll
    for (int ks = 0; ks < 4; ks++) {
        const int c = ks * 16 + 2 * tig;
        float2 x0 = *(const float2*)&s[r0 + c];
        float2 x1 = *(const float2*)&s[r1 + c];
        float2 x2 = *(const float2*)&s[r0 + c + 8];
        float2 x3 = *(const float2*)&s[r1 + c + 8];
        uint4 o;
        o.x = ph2(x0.x, x0.y);
        o.y = ph2(x1.x, x1.y);
        o.z = ph2(x2.x, x2.y);
        o.w = ph2(x3.x, x3.y);
        base[ks * 256] = o;
    }
}

__global__ void apack_qkv(const float* __restrict__ Q, const float* __restrict__ K,
                          const float* __restrict__ V)
{
    const int z = blockIdx.z;
    apack_body(z == 0 ? Q : z == 1 ? K : V,
               z == 0 ? g_qp : z == 1 ? g_kp : g_vp);
}

// ---------------- fp16 tensor-core GEMM, mbarrier-pipelined (no CTA barrier) ------
template <typename OutT>
__device__ __forceinline__ void gemm_body(const uint4* __restrict__ Ap,
                                          const uint4* __restrict__ Bp,
                                          const float* __restrict__ bias,
                                          OutT* __restrict__ C, OutT* __restrict__ C2,
                                          uint32_t sb)
{
    const int tid = threadIdx.x;
    const int wid = tid >> 5, lane = tid & 31;
    const int grp = lane >> 2, tig = lane & 3;
    const int wm = wid >> 1, wn = wid & 1;
    const int mblk = blockIdx.y, bx = blockIdx.x;
    const int nb2 = bx >> 1, bh = bx & 1;

    // mbarriers: full[0..2] then empty[0..2], 8B each
    const uint32_t mb = sb + 3 * STAGE_BYTES;
    if (tid == 0) {
#pragma unroll
        for (int s = 0; s < 3; s++) {
            MBAR_INIT(mb + s * 8, 256);        // full: 256 cp-completion arrivals
            MBAR_INIT(mb + 24 + s * 8, 256);   // empty: 256 consumer arrivals
        }
    }
    __syncthreads();

    float acc[2][4][4];
#pragma unroll
    for (int mi = 0; mi < 2; mi++)
#pragma unroll
        for (int ni = 0; ni < 4; ni++)
#pragma unroll
            for (int r = 0; r < 4; r++) acc[mi][ni][r] = 0.f;

    const uint4* Abase = Ap + (size_t)mblk * NT * CHUNK_U4 + tid * 4;
    const uint4* Bbase = Bp + (size_t)nb2 * NT * CHUNK_U4;
    const int j0 = tid * 2;
    const int koff0 = ((j0 >> 7) << 8) + bh * 128 + (j0 & 127);
    const int koff1 = (((j0 + 1) >> 7) << 8) + bh * 128 + ((j0 + 1) & 127);

    auto produce = [&](int pk) {
        const int s2 = pk % 3;
        if (pk >= 3) mbar_wait(mb + 24 + s2 * 8, ((pk / 3) - 1) & 1);
        const uint32_t da = sb + s2 * STAGE_BYTES + tid * 64;
        const uint4* sa = Abase + (size_t)pk * CHUNK_U4;
#pragma unroll
        for (int i = 0; i < 4; i++) cp_async16(da + i * 16, sa + i);
        const uint32_t db = sb + s2 * STAGE_BYTES + A_STAGE + tid * 32;
        const uint4* sbp = Bbase + (size_t)pk * CHUNK_U4;
        cp_async16(db,      sbp + koff0);
        cp_async16(db + 16, sbp + koff1);
        CP_MBAR_ARRIVE(mb + s2 * 8);
    };

    produce(0);
    produce(1);

    const uint32_t aOff = wm * 1024 + lane * 16;
    const uint32_t bOff = A_STAGE + wn * 1024 + lane * 16;

    int fph = 0;
    for (int kt = 0; kt < NT; kt++) {
        const int s = kt % 3;
        mbar_wait(mb + s * 8, fph);            // wait stage kt full
        if (kt + 2 < NT) produce(kt + 2);      // refill two ahead

        const uint32_t aBase = sb + s * STAGE_BYTES + aOff;
        const uint32_t bBase = sb + s * STAGE_BYTES + bOff;
#pragma unroll
        for (int ks = 0; ks < 4; ks++) {
            uint32_t a4[2][4], b4[2][4];
#pragma unroll
            for (int mi = 0; mi < 2; mi++)
                lds128(a4[mi][0], a4[mi][1], a4[mi][2], a4[mi][3],
                       aBase + ks * 4096 + mi * 512);
#pragma unroll
            for (int nb = 0; nb < 2; nb++)
                lds128(b4[nb][0], b4[nb][1], b4[nb][2], b4[nb][3],
                       bBase + ks * 2048 + nb * 512);
#pragma unroll
            for (int mi = 0; mi < 2; mi++) {
#pragma unroll
                for (int nb = 0; nb < 2; nb++) {
                    mma_f16(acc[mi][nb * 2 + 0], a4[mi], b4[nb][0], b4[nb][2]);
                    mma_f16(acc[mi][nb * 2 + 1], a4[mi], b4[nb][1], b4[nb][3]);
                }
            }
        }
        MBAR_ARRIVE(mb + 24 + s * 8);          // this thread done reading slot s
        if (s == 2) fph ^= 1;
    }

    const int n0 = bx * 64 + wn * 32;
    const int m0 = mblk * BM + wm * 32;
#pragma unroll
    for (int mi = 0; mi < 2; mi++) {
        const int r0 = m0 + mi * 16 + grp;
#pragma unroll
        for (int ni = 0; ni < 4; ni++) {
            const int col = n0 + (ni >> 1) * 16 + (ni & 1) * 8 + tig * 2;
            float2 bv = *(const float2*)&bias[col];
            store2(&C[(size_t)r0 * NDIM + col], acc[mi][ni][0] + bv.x, acc[mi][ni][1] + bv.y);
            store2(&C[(size_t)(r0 + 8) * NDIM + col], acc[mi][ni][2] + bv.x, acc[mi][ni][3] + bv.y);
            if (C2) {
                store2(&C2[(size_t)r0 * NDIM + col], acc[mi][ni][0] + bv.x, acc[mi][ni][1] + bv.y);
                store2(&C2[(size_t)(r0 + 8) * NDIM + col], acc[mi][ni][2] + bv.x, acc[mi][ni][3] + bv.y);
            }
        }
    }
}

__global__ void __launch_bounds__(256, 3) gemm_qkv(
    const float* __restrict__ bq, const float* __restrict__ bk, const float* __restrict__ bv,
    __half* __restrict__ Cq, __half* __restrict__ Ck, __half* __restrict__ Cv)
{
    extern __shared__ char smem[];
    const int z = blockIdx.z;
    gemm_body<__half>(z == 0 ? g_qp : z == 1 ? g_kp : g_vp,
                      g_wp + (size_t)z * W_PACK_U4,
                      z == 0 ? bq : z == 1 ? bk : bv,
                      z == 0 ? Cq : z == 1 ? Ck : Cv, (__half*)nullptr, smem_u32(smem));
}

__global__ void __launch_bounds__(256, 3) gemm_out(
    const float* __restrict__ bias, float* __restrict__ C, float* __restrict__ C2)
{
    extern __shared__ char smem[];
    gemm_body<float>(g_ap, g_wp + 3ull * W_PACK_U4, bias, C, C2, smem_u32(smem));
}

// ---------------- fused tensor-core attention + fragment pack ----------------
#define ATW 8
#define STG_H 3456
#define SOUT_TS 1096
#define SOUT_HS 68
#define ATTN_SMEM ((ATW * STG_H + 16 * SOUT_TS) * 2)

__global__ void __launch_bounds__(256) attn_pack(
    const __half* __restrict__ qg, const __half* __restrict__ kg,
    const __half* __restrict__ vg, const float* __restrict__ mg)
{
    extern __shared__ __half smh[];
    const int warp = threadIdx.x >> 5, lane = threadIdx.x & 31;
    const int grp = lane >> 2, tig = lane & 3;
    __half* sq = smh + warp * STG_H;
    __half* sk = sq + 16 * 72;
    __half* sv = sk + 16 * 72;
    __half* sout = smh + ATW * STG_H;
    const uint32_t sqa = smem_u32(sq), ska = smem_u32(sk), sva = smem_u32(sv);

    const int lrow = (lane & 7) + ((lane >> 3) & 1) * 8;
    const int lc8  = (lane >> 4) * 8;

#pragma unroll
    for (int pass = 0; pass < 2; pass++) {
        const int lt = warp + pass * 8;
        const int tok = blockIdx.x * 16 + lt;
        const size_t base = (size_t)tok * 1024;

#pragma unroll
        for (int i = 0; i < 4; i++) {
            int idx = lane + i * 32;
            int row = idx >> 3, cq = (idx & 7) * 8;
            *(uint4*)&sq[row * 72 + cq] = *(const uint4*)&qg[base + row * 64 + cq];
            *(uint4*)&sk[row * 72 + cq] = *(const uint4*)&kg[base + row * 64 + cq];
            *(uint4*)&sv[row * 72 + cq] = *(const uint4*)&vg[base + row * 64 + cq];
        }
        __syncwarp();

        float s0[4] = {0.f, 0.f, 0.f, 0.f}, s1[4] = {0.f, 0.f, 0.f, 0.f};
#pragma unroll
        for (int ks = 0; ks < 4; ks++) {
            uint32_t qa[4], kb[4];
            ldsm4(qa, sqa + (lrow * 72 + ks * 16 + lc8) * 2);
            ldsm4(kb, ska + (lrow * 72 + ks * 16 + lc8) * 2);
            mma_f16(s0, qa, kb[0], kb[2]);
            mma_f16(s1, qa, kb[1], kb[3]);
        }

        const float* mp = mg + (size_t)tok * 256;
        float2 m00 = *(const float2*)&mp[grp * 16 + 2 * tig];
        float2 m01 = *(const float2*)&mp[grp * 16 + 8 + 2 * tig];
        float2 m10 = *(const float2*)&mp[(grp + 8) * 16 + 2 * tig];
        float2 m11 = *(const float2*)&mp[(grp + 8) * 16 + 8 + 2 * tig];
        float a0 = fmaf(m00.x, -1e9f, s0[0] * 0.125f);
        float a1 = fmaf(m00.y, -1e9f, s0[1] * 0.125f);
        float a2 = fmaf(m10.x, -1e9f, s0[2] * 0.125f);
        float a3 = fmaf(m10.y, -1e9f, s0[3] * 0.125f);
        float a4 = fmaf(m01.x, -1e9f, s1[0] * 0.125f);
        float a5 = fmaf(m01.y, -1e9f, s1[1] * 0.125f);
        float a6 = fmaf(m11.x, -1e9f, s1[2] * 0.125f);
        float a7 = fmaf(m11.y, -1e9f, s1[3] * 0.125f);

        float mxA = fmaxf(fmaxf(a0, a1), fmaxf(a4, a5));
        float mxB = fmaxf(fmaxf(a2, a3), fmaxf(a6, a7));
        mxA = fmaxf(mxA, __shfl_xor_sync(0xffffffffu, mxA, 1));
        mxA = fmaxf(mxA, __shfl_xor_sync(0xffffffffu, mxA, 2));
        mxB = fmaxf(mxB, __shfl_xor_sync(0xffffffffu, mxB, 1));
        mxB = fmaxf(mxB, __shfl_xor_sync(0xffffffffu, mxB, 2));

        float e0 = __expf(a0 - mxA), e1 = __expf(a1 - mxA);
        float e4 = __expf(a4 - mxA), e5 = __expf(a5 - mxA);
        float e2 = __expf(a2 - mxB), e3 = __expf(a3 - mxB);
        float e6 = __expf(a6 - mxB), e7 = __expf(a7 - mxB);

        float sA = e0 + e1 + e4 + e5;
        float sB = e2 + e3 + e6 + e7;
        sA += __shfl_xor_sync(0xffffffffu, sA, 1);
        sA += __shfl_xor_sync(0xffffffffu, sA, 2);
        sB += __shfl_xor_sync(0xffffffffu, sB, 1);
        sB += __shfl_xor_sync(0xffffffffu, sB, 2);
        const float iA = 1.0f / sA, iB = 1.0f / sB;

        uint32_t pf[4];
        pf[0] = ph2(e0 * iA, e1 * iA);
        pf[1] = ph2(e2 * iB, e3 * iB);
        pf[2] = ph2(e4 * iA, e5 * iA);
        pf[3] = ph2(e6 * iB, e7 * iB);

        float oc[8][4];
#pragma unroll
        for (int nt = 0; nt < 8; nt++)
#pragma unroll
            for (int r = 0; r < 4; r++) oc[nt][r] = 0.f;
#pragma unroll
        for (int cc = 0; cc < 4; cc++) {
            uint32_t vb[4];
            ldsm4t(vb, sva + (lrow * 72 + cc * 16 + lc8) * 2);
            mma_f16(oc[cc * 2 + 0], pf, vb[0], vb[1]);
            mma_f16(oc[cc * 2 + 1], pf, vb[2], vb[3]);
        }

        __half* so = sout + lt * SOUT_TS;
#pragma unroll
        for (int nt = 0; nt < 8; nt++) {
            *(uint32_t*)&so[grp * SOUT_HS + nt * 8 + 2 * tig]       = ph2(oc[nt][0], oc[nt][1]);
            *(uint32_t*)&so[(grp + 8) * SOUT_HS + nt * 8 + 2 * tig] = ph2(oc[nt][2], oc[nt][3]);
        }
        __syncwarp();
    }
    __syncthreads();

    const int mblk = blockIdx.x >> 3, b = blockIdx.x & 7;
#pragma unroll
    for (int i = 0; i < 8; i++) {
        const int g = warp * 8 + i;
        const int kt = g >> 2, ks = g & 3;
        const __half* s0p = sout + grp * SOUT_TS + kt * SOUT_HS + ks * 16 + 2 * tig;
        const __half* s1p = s0p + 8 * SOUT_TS;
        uint4 o;
        o.x = *(const uint32_t*)s0p;
        o.y = *(const uint32_t*)s1p;
        o.z = *(const uint32_t*)(s0p + 8);
        o.w = *(const uint32_t*)(s1p + 8);
        g_ap[((size_t)(mblk * NT + kt)) * CHUNK_U4 + ks * 256 + b * 32 + lane] = o;
    }
}

// ---------------- launch ----------------
extern "C" void kernel_launch(void* const* d_in, const int* in_sizes, int n_in,
                              void* d_out, int out_size)
{
    const float* Q  = (const float*)d_in[0];
    const float* K  = (const float*)d_in[1];
    const float* V  = (const float*)d_in[2];
    const float* Msk= (const float*)d_in[3];
    const float* Wq = (const float*)d_in[4];
    const float* bq = (const float*)d_in[5];
    const float* Wk = (const float*)d_in[6];
    const float* bk = (const float*)d_in[7];
    const float* Wv = (const float*)d_in[8];
    const float* bv = (const float*)d_in[9];
    const float* Wo = (const float*)d_in[10];
    const float* bo = (const float*)d_in[11];
    float* out = (float*)d_out;

    __half *gq, *gk, *gv;
    uint4* gwp;
    cudaGetSymbolAddress((void**)&gq, g_q);
    cudaGetSymbolAddress((void**)&gk, g_k);
    cudaGetSymbolAddress((void**)&gv, g_v);
    cudaGetSymbolAddress((void**)&gwp, g_wp);

    cudaFuncSetAttribute(gemm_qkv, cudaFuncAttributeMaxDynamicSharedMemorySize, GEMM_SMEM);
    cudaFuncSetAttribute(gemm_out, cudaFuncAttributeMaxDynamicSharedMemorySize, GEMM_SMEM);
    cudaFuncSetAttribute(attn_pack, cudaFuncAttributeMaxDynamicSharedMemorySize, ATTN_SMEM);

    // 1. pack weights + input activations
    wpack<<<dim3(NT, NDIM / 128, 4), 256>>>(Wq, Wk, Wv, Wo, gwp);
    apack_qkv<<<dim3(NT, MDIM / 128, 3), 256>>>(Q, K, V);

    // 2. QKV projections (fp16 out, mbarrier-pipelined)
    dim3 gg(NDIM / BN, MDIM / BM, 3);
    gemm_qkv<<<gg, 256, GEMM_SMEM>>>(bq, bk, bv, gq, gk, gv);

    // 3. fused tensor-core attention + fragment pack (writes g_ap directly)
    attn_pack<<<MDIM / 16, 256, ATTN_SMEM>>>(gq, gk, gv, Msk);

    // 4. output projection
    float* out2 = ((long long)out_size >= 2LL * MDIM * NDIM) ? out + (size_t)MDIM * NDIM
                                                             : nullptr;
    dim3 go(NDIM / BN, MDIM / BM);
    gemm_out<<<go, 256, GEMM_SMEM>>>(bo, out, out2);
}

// round 15
// speedup vs baseline: 1.4575x; 1.0206x over previous
#include <cuda_runtime.h>
#include <cuda_fp16.h>
#include <cstdint>

// ---------------- problem dims ----------------
#define MDIM 16384   // B*S
#define NDIM 1024    // DM
#define KDIM 1024    // DM

// ---------------- GEMM tiling ----------------
#define BM 128
#define BN 64
#define BK 64
#define NT (KDIM / BK)              // 16 k-stages
#define A_STAGE 16384               // 128x64 fp16
#define B_STAGE 8192                // 64x64 fp16
#define STAGE_BYTES (A_STAGE + B_STAGE)   // 24KB
#define GEMM_SMEM (3 * STAGE_BYTES + 64)  // + mbarrier block

// packed sizes (uint4 units). chunk = 128 rows x 64 cols fp16 = 16KB = 1024 uint4
#define CHUNK_U4   1024
#define ACT_CHUNKS ((MDIM / 128) * NT)
#define W_CHUNKS   ((NDIM / 128) * NT)
#define ACT_PACK_U4 ((size_t)ACT_CHUNKS * CHUNK_U4)
#define W_PACK_U4   ((size_t)W_CHUNKS * CHUNK_U4)

// ---------------- scratch (no allocs allowed) ----------------
__device__ __half g_q[(size_t)MDIM * NDIM];
__device__ __half g_k[(size_t)MDIM * NDIM];
__device__ __half g_v[(size_t)MDIM * NDIM];
__device__ uint4  g_wp[4ull * W_PACK_U4];              // packed fp16 weights
__device__ uint4  g_qp[ACT_PACK_U4];
__device__ uint4  g_kp[ACT_PACK_U4];
__device__ uint4  g_vp[ACT_PACK_U4];
__device__ uint4  g_ap[ACT_PACK_U4];                   // packed attn output

// ---------------- helpers ----------------
__device__ __forceinline__ uint32_t smem_u32(const void* p) {
    uint32_t a;
    asm("{ .reg .u64 t; cvta.to.shared.u64 t, %1; cvt.u32.u64 %0, t; }" : "=r"(a) : "l"(p));
    return a;
}

__device__ __forceinline__ void cp_async16(uint32_t saddr, const void* gaddr) {
    asm volatile("cp.async.cg.shared.global [%0], [%1], 16;\n" :: "r"(saddr), "l"(gaddr));
}

__device__ __forceinline__ void lds128(uint32_t& a, uint32_t& b, uint32_t& c, uint32_t& d,
                                       uint32_t addr) {
    asm volatile("ld.shared.v4.b32 {%0,%1,%2,%3}, [%4];"
                 : "=r"(a), "=r"(b), "=r"(c), "=r"(d) : "r"(addr));
}

__device__ __forceinline__ void mma_f16(float c[4], const uint32_t a[4],
                                        uint32_t b0, uint32_t b1) {
    asm volatile(
        "mma.sync.aligned.m16n8k16.row.col.f32.f16.f16.f32 "
        "{%0,%1,%2,%3}, {%4,%5,%6,%7}, {%8,%9}, {%0,%1,%2,%3};\n"
        : "+f"(c[0]), "+f"(c[1]), "+f"(c[2]), "+f"(c[3])
        : "r"(a[0]), "r"(a[1]), "r"(a[2]), "r"(a[3]), "r"(b0), "r"(b1));
}

__device__ __forceinline__ void ldsm4(uint32_t r[4], uint32_t addr) {
    asm volatile("ldmatrix.sync.aligned.m8n8.x4.shared.b16 {%0,%1,%2,%3}, [%4];"
                 : "=r"(r[0]), "=r"(r[1]), "=r"(r[2]), "=r"(r[3]) : "r"(addr));
}

__device__ __forceinline__ void ldsm4t(uint32_t r[4], uint32_t addr) {
    asm volatile("ldmatrix.sync.aligned.m8n8.x4.trans.shared.b16 {%0,%1,%2,%3}, [%4];"
                 : "=r"(r[0]), "=r"(r[1]), "=r"(r[2]), "=r"(r[3]) : "r"(addr));
}

__device__ __forceinline__ uint32_t ph2(float lo, float hi) {
    __half2 h = __floats2half2_rn(lo, hi);
    return *reinterpret_cast<uint32_t*>(&h);
}

__device__ __forceinline__ void store2(float* p, float a, float b) {
    *(float2*)p = make_float2(a, b);
}
__device__ __forceinline__ void store2(__half* p, float a, float b) {
    *(uint32_t*)p = ph2(a, b);
}

#define MBAR_INIT(a, n) asm volatile("mbarrier.init.shared.b64 [%0], %1;" :: "r"(a), "r"(n) : "memory")
#define MBAR_ARRIVE(a)  asm volatile("mbarrier.arrive.shared.b64 _, [%0];" :: "r"(a) : "memory")
#define CP_MBAR_ARRIVE(a) asm volatile("cp.async.mbarrier.arrive.noinc.shared.b64 [%0];" :: "r"(a) : "memory")

__device__ __forceinline__ void mbar_wait(uint32_t addr, uint32_t parity) {
    uint32_t done;
    asm volatile("{ .reg .pred p; mbarrier.try_wait.parity.acquire.cta.shared::cta.b64 p, [%1], %2; selp.b32 %0,1,0,p; }"
                 : "=r"(done) : "r"(addr), "r"(parity) : "memory");
    if (!done) {
        asm volatile(
            "{ .reg .pred P1;\n"
            "W_%=: mbarrier.try_wait.parity.acquire.cta.shared::cta.b64 P1, [%0], %1, 0x989680;\n"
            "@P1 bra.uni D_%=;\n"
            "bra.uni W_%=;\n"
            "D_%=: }" :: "r"(addr), "r"(parity) : "memory");
    }
}

// ---------------- weight pack: W[k][n] f32 -> fragment-packed fp16 ----------
__global__ void wpack(const float* __restrict__ W0, const float* __restrict__ W1,
                      const float* __restrict__ W2, const float* __restrict__ W3,
                      uint4* __restrict__ out)
{
    __shared__ float s[128 * 66];
    const int z = blockIdx.z;
    const float* W = (z == 0) ? W0 : (z == 1) ? W1 : (z == 2) ? W2 : W3;
    uint4* dst = out + (size_t)z * W_PACK_U4
               + ((size_t)(blockIdx.y * NT + blockIdx.x)) * CHUNK_U4;
    const int t = threadIdx.x;
    const int kt = blockIdx.x, nblk = blockIdx.y;
#pragma unroll
    for (int i = 0; i < 32; i++) {
        int idx = t + i * 256;
        int k = idx >> 7, n = idx & 127;
        s[n * 66 + k] = W[(size_t)(kt * 64 + k) * NDIM + nblk * 128 + n];
    }
    __syncthreads();
    const int b = t >> 5, l = t & 31, grp = l >> 2, tig = l & 3;
    const int r0 = (b * 16 + grp) * 66, r1 = r0 + 8 * 66;
    uint4* base = dst + b * 32 + l;
#pragma unroll
    for (int ks = 0; ks < 4; ks++) {
        const int c = ks * 16 + 2 * tig;
        float2 x0 = *(const float2*)&s[r0 + c];
        float2 x1 = *(const float2*)&s[r1 + c];
        float2 x2 = *(const float2*)&s[r0 + c + 8];
        float2 x3 = *(const float2*)&s[r1 + c + 8];
        uint4 o;
        o.x = ph2(x0.x, x0.y);
        o.y = ph2(x1.x, x1.y);
        o.z = ph2(x2.x, x2.y);
        o.w = ph2(x3.x, x3.y);
        base[ks * 256] = o;
    }
}

// ---------------- activation pack: direct GMEM -> fp16 frags (no smem staging) ----
// Each thread emits 4 packed uint4 words; sources are 16 independent 8B loads.
// Quad (4 lanes, tig 0..3) reads 4x8B = one full 32B sector per (row, 16-col group).
__device__ __forceinline__ void apack_body(const float* __restrict__ src,
                                           uint4* __restrict__ dst)
{
    const int t = threadIdx.x;
    const int mblk = blockIdx.y, kt = blockIdx.x;
    const int b = t >> 5, l = t & 31, grp = l >> 2, tig = l & 3;
    const size_t r0 = (size_t)(mblk * 128 + b * 16 + grp) * KDIM + kt * 64;
    const size_t r1 = r0 + 8 * KDIM;
    uint4* base = dst + ((size_t)(mblk * NT + kt)) * CHUNK_U4 + b * 32 + l;
#pragma unroll
    for (int ks = 0; ks < 4; ks++) {
        const int c = ks * 16 + 2 * tig;
        float2 x0 = *(const float2*)&src[r0 + c];
        float2 x1 = *(const float2*)&src[r1 + c];
        float2 x2 = *(const float2*)&src[r0 + c + 8];
        float2 x3 = *(const float2*)&src[r1 + c + 8];
        uint4 o;
        o.x = ph2(x0.x, x0.y);
        o.y = ph2(x1.x, x1.y);
        o.z = ph2(x2.x, x2.y);
        o.w = ph2(x3.x, x3.y);
        base[ks * 256] = o;
    }
}

__global__ void apack_qkv(const float* __restrict__ Q, const float* __restrict__ K,
                          const float* __restrict__ V)
{
    const int z = blockIdx.z;
    apack_body(z == 0 ? Q : z == 1 ? K : V,
               z == 0 ? g_qp : z == 1 ? g_kp : g_vp);
}

// ---------------- fp16 tensor-core GEMM, mbarrier-pipelined (no CTA barrier) ------
template <typename OutT>
__device__ __forceinline__ void gemm_body(const uint4* __restrict__ Ap,
                                          const uint4* __restrict__ Bp,
                                          const float* __restrict__ bias,
                                          OutT* __restrict__ C, OutT* __restrict__ C2,
                                          uint32_t sb)
{
    const int tid = threadIdx.x;
    const int wid = tid >> 5, lane = tid & 31;
    const int grp = lane >> 2, tig = lane & 3;
    const int wm = wid >> 1, wn = wid & 1;
    const int mblk = blockIdx.y, bx = blockIdx.x;
    const int nb2 = bx >> 1, bh = bx & 1;

    // mbarriers: full[0..2] then empty[0..2], 8B each
    const uint32_t mb = sb + 3 * STAGE_BYTES;
    if (tid == 0) {
#pragma unroll
        for (int s = 0; s < 3; s++) {
            MBAR_INIT(mb + s * 8, 256);        // full: 256 cp-completion arrivals
            MBAR_INIT(mb + 24 + s * 8, 256);   // empty: 256 consumer arrivals
        }
    }
    __syncthreads();

    float acc[2][4][4];
#pragma unroll
    for (int mi = 0; mi < 2; mi++)
#pragma unroll
        for (int ni = 0; ni < 4; ni++)
#pragma unroll
            for (int r = 0; r < 4; r++) acc[mi][ni][r] = 0.f;

    const uint4* Abase = Ap + (size_t)mblk * NT * CHUNK_U4 + tid * 4;
    const uint4* Bbase = Bp + (size_t)nb2 * NT * CHUNK_U4;
    const int j0 = tid * 2;
    const int koff0 = ((j0 >> 7) << 8) + bh * 128 + (j0 & 127);
    const int koff1 = (((j0 + 1) >> 7) << 8) + bh * 128 + ((j0 + 1) & 127);

    auto produce = [&](int pk) {
        const int s2 = pk % 3;
        if (pk >= 3) mbar_wait(mb + 24 + s2 * 8, ((pk / 3) - 1) & 1);
        const uint32_t da = sb + s2 * STAGE_BYTES + tid * 64;
        const uint4* sa = Abase + (size_t)pk * CHUNK_U4;
#pragma unroll
        for (int i = 0; i < 4; i++) cp_async16(da + i * 16, sa + i);
        const uint32_t db = sb + s2 * STAGE_BYTES + A_STAGE + tid * 32;
        const uint4* sbp = Bbase + (size_t)pk * CHUNK_U4;
        cp_async16(db,      sbp + koff0);
        cp_async16(db + 16, sbp + koff1);
        CP_MBAR_ARRIVE(mb + s2 * 8);
    };

    produce(0);
    produce(1);

    const uint32_t aOff = wm * 1024 + lane * 16;
    const uint32_t bOff = A_STAGE + wn * 1024 + lane * 16;

    int fph = 0;
    for (int kt = 0; kt < NT; kt++) {
        const int s = kt % 3;
        mbar_wait(mb + s * 8, fph);            // wait stage kt full
        if (kt + 2 < NT) produce(kt + 2);      // refill two ahead

        const uint32_t aBase = sb + s * STAGE_BYTES + aOff;
        const uint32_t bBase = sb + s * STAGE_BYTES + bOff;
#pragma unroll
        for (int ks = 0; ks < 4; ks++) {
            uint32_t a4[2][4], b4[2][4];
#pragma unroll
            for (int mi = 0; mi < 2; mi++)
                lds128(a4[mi][0], a4[mi][1], a4[mi][2], a4[mi][3],
                       aBase + ks * 4096 + mi * 512);
#pragma unroll
            for (int nb = 0; nb < 2; nb++)
                lds128(b4[nb][0], b4[nb][1], b4[nb][2], b4[nb][3],
                       bBase + ks * 2048 + nb * 512);
#pragma unroll
            for (int mi = 0; mi < 2; mi++) {
#pragma unroll
                for (int nb = 0; nb < 2; nb++) {
                    mma_f16(acc[mi][nb * 2 + 0], a4[mi], b4[nb][0], b4[nb][2]);
                    mma_f16(acc[mi][nb * 2 + 1], a4[mi], b4[nb][1], b4[nb][3]);
                }
            }
        }
        MBAR_ARRIVE(mb + 24 + s * 8);          // this thread done reading slot s
        if (s == 2) fph ^= 1;
    }

    const int n0 = bx * 64 + wn * 32;
    const int m0 = mblk * BM + wm * 32;
#pragma unroll
    for (int mi = 0; mi < 2; mi++) {
        const int r0 = m0 + mi * 16 + grp;
#pragma unroll
        for (int ni = 0; ni < 4; ni++) {
            const int col = n0 + (ni >> 1) * 16 + (ni & 1) * 8 + tig * 2;
            float2 bv = *(const float2*)&bias[col];
            store2(&C[(size_t)r0 * NDIM + col], acc[mi][ni][0] + bv.x, acc[mi][ni][1] + bv.y);
            store2(&C[(size_t)(r0 + 8) * NDIM + col], acc[mi][ni][2] + bv.x, acc[mi][ni][3] + bv.y);
            if (C2) {
                store2(&C2[(size_t)r0 * NDIM + col], acc[mi][ni][0] + bv.x, acc[mi][ni][1] + bv.y);
                store2(&C2[(size_t)(r0 + 8) * NDIM + col], acc[mi][ni][2] + bv.x, acc[mi][ni][3] + bv.y);
            }
        }
    }
}

__global__ void __launch_bounds__(256, 3) gemm_qkv(
    const float* __restrict__ bq, const float* __restrict__ bk, const float* __restrict__ bv,
    __half* __restrict__ Cq, __half* __restrict__ Ck, __half* __restrict__ Cv)
{
    extern __shared__ char smem[];
    const int z = blockIdx.z;
    gemm_body<__half>(z == 0 ? g_qp : z == 1 ? g_kp : g_vp,
                      g_wp + (size_t)z * W_PACK_U4,
                      z == 0 ? bq : z == 1 ? bk : bv,
                      z == 0 ? Cq : z == 1 ? Ck : Cv, (__half*)nullptr, smem_u32(smem));
}

__global__ void __launch_bounds__(256, 3) gemm_out(
    const float* __restrict__ bias, float* __restrict__ C, float* __restrict__ C2)
{
    extern __shared__ char smem[];
    gemm_body<float>(g_ap, g_wp + 3ull * W_PACK_U4, bias, C, C2, smem_u32(smem));
}

// ---------------- fused tensor-core attention + fragment pack ----------------
#define ATW 8
#define STG_H 3456
#define SOUT_TS 1096
#define SOUT_HS 68
#define ATTN_SMEM ((ATW * STG_H + 16 * SOUT_TS) * 2)

__global__ void __launch_bounds__(256) attn_pack(
    const __half* __restrict__ qg, const __half* __restrict__ kg,
    const __half* __restrict__ vg, const float* __restrict__ mg)
{
    extern __shared__ __half smh[];
    const int warp = threadIdx.x >> 5, lane = threadIdx.x & 31;
    const int grp = lane >> 2, tig = lane & 3;
    __half* sq = smh + warp * STG_H;
    __half* sk = sq + 16 * 72;
    __half* sv = sk + 16 * 72;
    __half* sout = smh + ATW * STG_H;
    const uint32_t sqa = smem_u32(sq), ska = smem_u32(sk), sva = smem_u32(sv);

    const int lrow = (lane & 7) + ((lane >> 3) & 1) * 8;
    const int lc8  = (lane >> 4) * 8;

#pragma unroll
    for (int pass = 0; pass < 2; pass++) {
        const int lt = warp + pass * 8;
        const int tok = blockIdx.x * 16 + lt;
        const size_t base = (size_t)tok * 1024;

#pragma unroll
        for (int i = 0; i < 4; i++) {
            int idx = lane + i * 32;
            int row = idx >> 3, cq = (idx & 7) * 8;
            *(uint4*)&sq[row * 72 + cq] = *(const uint4*)&qg[base + row * 64 + cq];
            *(uint4*)&sk[row * 72 + cq] = *(const uint4*)&kg[base + row * 64 + cq];
            *(uint4*)&sv[row * 72 + cq] = *(const uint4*)&vg[base + row * 64 + cq];
        }
        __syncwarp();

        float s0[4] = {0.f, 0.f, 0.f, 0.f}, s1[4] = {0.f, 0.f, 0.f, 0.f};
#pragma unroll
        for (int ks = 0; ks < 4; ks++) {
            uint32_t qa[4], kb[4];
            ldsm4(qa, sqa + (lrow * 72 + ks * 16 + lc8) * 2);
            ldsm4(kb, ska + (lrow * 72 + ks * 16 + lc8) * 2);
            mma_f16(s0, qa, kb[0], kb[2]);
            mma_f16(s1, qa, kb[1], kb[3]);
        }

        const float* mp = mg + (size_t)tok * 256;
        float2 m00 = *(const float2*)&mp[grp * 16 + 2 * tig];
        float2 m01 = *(const float2*)&mp[grp * 16 + 8 + 2 * tig];
        float2 m10 = *(const float2*)&mp[(grp + 8) * 16 + 2 * tig];
        float2 m11 = *(const float2*)&mp[(grp + 8) * 16 + 8 + 2 * tig];
        float a0 = fmaf(m00.x, -1e9f, s0[0] * 0.125f);
        float a1 = fmaf(m00.y, -1e9f, s0[1] * 0.125f);
        float a2 = fmaf(m10.x, -1e9f, s0[2] * 0.125f);
        float a3 = fmaf(m10.y, -1e9f, s0[3] * 0.125f);
        float a4 = fmaf(m01.x, -1e9f, s1[0] * 0.125f);
        float a5 = fmaf(m01.y, -1e9f, s1[1] * 0.125f);
        float a6 = fmaf(m11.x, -1e9f, s1[2] * 0.125f);
        float a7 = fmaf(m11.y, -1e9f, s1[3] * 0.125f);

        float mxA = fmaxf(fmaxf(a0, a1), fmaxf(a4, a5));
        float mxB = fmaxf(fmaxf(a2, a3), fmaxf(a6, a7));
        mxA = fmaxf(mxA, __shfl_xor_sync(0xffffffffu, mxA, 1));
        mxA = fmaxf(mxA, __shfl_xor_sync(0xffffffffu, mxA, 2));
        mxB = fmaxf(mxB, __shfl_xor_sync(0xffffffffu, mxB, 1));
        mxB = fmaxf(mxB, __shfl_xor_sync(0xffffffffu, mxB, 2));

        float e0 = __expf(a0 - mxA), e1 = __expf(a1 - mxA);
        float e4 = __expf(a4 - mxA), e5 = __expf(a5 - mxA);
        float e2 = __expf(a2 - mxB), e3 = __expf(a3 - mxB);
        float e6 = __expf(a6 - mxB), e7 = __expf(a7 - mxB);

        float sA = e0 + e1 + e4 + e5;
        float sB = e2 + e3 + e6 + e7;
        sA += __shfl_xor_sync(0xffffffffu, sA, 1);
        sA += __shfl_xor_sync(0xffffffffu, sA, 2);
        sB += __shfl_xor_sync(0xffffffffu, sB, 1);
        sB += __shfl_xor_sync(0xffffffffu, sB, 2);
        const float iA = 1.0f / sA, iB = 1.0f / sB;

        uint32_t pf[4];
        pf[0] = ph2(e0 * iA, e1 * iA);
        pf[1] = ph2(e2 * iB, e3 * iB);
        pf[2] = ph2(e4 * iA, e5 * iA);
        pf[3] = ph2(e6 * iB, e7 * iB);

        float oc[8][4];
#pragma unroll
        for (int nt = 0; nt < 8; nt++)
#pragma unroll
            for (int r = 0; r < 4; r++) oc[nt][r] = 0.f;
#pragma unroll
        for (int cc = 0; cc < 4; cc++) {
            uint32_t vb[4];
            ldsm4t(vb, sva + (lrow * 72 + cc * 16 + lc8) * 2);
            mma_f16(oc[cc * 2 + 0], pf, vb[0], vb[1]);
            mma_f16(oc[cc * 2 + 1], pf, vb[2], vb[3]);
        }

        __half* so = sout + lt * SOUT_TS;
#pragma unroll
        for (int nt = 0; nt < 8; nt++) {
            *(uint32_t*)&so[grp * SOUT_HS + nt * 8 + 2 * tig]       = ph2(oc[nt][0], oc[nt][1]);
            *(uint32_t*)&so[(grp + 8) * SOUT_HS + nt * 8 + 2 * tig] = ph2(oc[nt][2], oc[nt][3]);
        }
        __syncwarp();
    }
    __syncthreads();

    const int mblk = blockIdx.x >> 3, b = blockIdx.x & 7;
#pragma unroll
    for (int i = 0; i < 8; i++) {
        const int g = warp * 8 + i;
        const int kt = g >> 2, ks = g & 3;
        const __half* s0p = sout + grp * SOUT_TS + kt * SOUT_HS + ks * 16 + 2 * tig;
        const __half* s1p = s0p + 8 * SOUT_TS;
        uint4 o;
        o.x = *(const uint32_t*)s0p;
        o.y = *(const uint32_t*)s1p;
        o.z = *(const uint32_t*)(s0p + 8);
        o.w = *(const uint32_t*)(s1p + 8);
        g_ap[((size_t)(mblk * NT + kt)) * CHUNK_U4 + ks * 256 + b * 32 + lane] = o;
    }
}

// ---------------- launch ----------------
extern "C" void kernel_launch(void* const* d_in, const int* in_sizes, int n_in,
                              void* d_out, int out_size)
{
    const float* Q  = (const float*)d_in[0];
    const float* K  = (const float*)d_in[1];
    const float* V  = (const float*)d_in[2];
    const float* Msk= (const float*)d_in[3];
    const float* Wq = (const float*)d_in[4];
    const float* bq = (const float*)d_in[5];
    const float* Wk = (const float*)d_in[6];
    const float* bk = (const float*)d_in[7];
    const float* Wv = (const float*)d_in[8];
    const float* bv = (const float*)d_in[9];
    const float* Wo = (const float*)d_in[10];
    const float* bo = (const float*)d_in[11];
    float* out = (float*)d_out;

    __half *gq, *gk, *gv;
    uint4* gwp;
    cudaGetSymbolAddress((void**)&gq, g_q);
    cudaGetSymbolAddress((void**)&gk, g_k);
    cudaGetSymbolAddress((void**)&gv, g_v);
    cudaGetSymbolAddress((void**)&gwp, g_wp);

    cudaFuncSetAttribute(gemm_qkv, cudaFuncAttributeMaxDynamicSharedMemorySize, GEMM_SMEM);
    cudaFuncSetAttribute(gemm_out, cudaFuncAttributeMaxDynamicSharedMemorySize, GEMM_SMEM);
    cudaFuncSetAttribute(attn_pack, cudaFuncAttributeMaxDynamicSharedMemorySize, ATTN_SMEM);

    // 1. pack weights + input activations (apack: direct-GMEM, no smem staging)
    wpack<<<dim3(NT, NDIM / 128, 4), 256>>>(Wq, Wk, Wv, Wo, gwp);
    apack_qkv<<<dim3(NT, MDIM / 128, 3), 256>>>(Q, K, V);

    // 2. QKV projections (fp16 out, mbarrier-pipelined)
    dim3 gg(NDIM / BN, MDIM / BM, 3);
    gemm_qkv<<<gg, 256, GEMM_SMEM>>>(bq, bk, bv, gq, gk, gv);

    // 3. fused tensor-core attention + fragment pack (writes g_ap directly)
    attn_pack<<<MDIM / 16, 256, ATTN_SMEM>>>(gq, gk, gv, Msk);

    // 4. output projection
    float* out2 = ((long long)out_size >= 2LL * MDIM * NDIM) ? out + (size_t)MDIM * NDIM
                                                             : nullptr;
    dim3 go(NDIM / BN, MDIM / BM);
    gemm_out<<<go, 256, GEMM_SMEM>>>(bo, out, out2);
}